// round 2
// baseline (speedup 1.0000x reference)
#include <cuda_runtime.h>
#include <cstddef>
#include <cstdint>

// Problem constants
#define S_  2048
#define B_  2
#define E_  1024
#define H_  16
#define HD_ 64
#define M_  (S_ * B_)      // 4096 rows for projection GEMMs
#define RS_ (B_ * E_)      // 2048 floats: stride between consecutive s in [S,B,E]

// Scratch buffers (device globals; no cudaMalloc allowed)
__device__ __align__(128) float g_q[(size_t)M_ * E_];
__device__ __align__(128) float g_k[(size_t)M_ * E_];
__device__ __align__(128) float g_v[(size_t)M_ * E_];
__device__ __align__(128) float g_o[(size_t)M_ * E_];

// Device-side scratch selection (avoids host cudaGetSymbolAddress entirely)
__device__ __forceinline__ float* pick_out(int w, float* ext) {
    switch (w) {
        case 0: return g_q;
        case 1: return g_k;
        case 2: return g_v;
        default: return ext;
    }
}
__device__ __forceinline__ const float* pick_in(int w, const float* ext) {
    return (w == 1) ? (const float*)g_o : ext;
}

// ---------------------------------------------------------------------------
// GEMM: C[m,n] = sum_k A[m,k] * W[n,k] + bias[n]
// A: MxK row-major, W: NxK row-major ("NT"). Fixed K = E_ = 1024.
// Block tile 128x128, K-tile 8, 256 threads, 8x8 microtile, double-buffered.
// which_in:  0 -> A = Aext, 1 -> A = g_o
// which_out: 0/1/2 -> g_q/g_k/g_v, 3 -> Cext
// ---------------------------------------------------------------------------
__global__ void __launch_bounds__(256)
gemm_nt_bias(const float* __restrict__ Aext, const float* __restrict__ W,
             const float* __restrict__ bias, float* __restrict__ Cext,
             int which_in, int which_out)
{
    __shared__ float As[2][8][132];
    __shared__ float Bs[2][8][132];

    const float* A = pick_in(which_in, Aext);
    float* C = pick_out(which_out, Cext);

    const int tid = threadIdx.x;
    const int tx = tid & 15;
    const int ty = tid >> 4;
    const int bm = blockIdx.y * 128;
    const int bn = blockIdx.x * 128;

    const int ldRow = tid >> 1;          // 0..127
    const int ldCol = (tid & 1) * 4;     // 0 or 4

    const float* Ap = A + (size_t)(bm + ldRow) * E_ + ldCol;
    const float* Wp = W + (size_t)(bn + ldRow) * E_ + ldCol;

    float acc[8][8];
#pragma unroll
    for (int i = 0; i < 8; i++)
#pragma unroll
        for (int j = 0; j < 8; j++) acc[i][j] = 0.f;

    // Preload tile 0 into smem buffer 0
    {
        const float4 av = *(const float4*)(Ap);
        const float4 wv = *(const float4*)(Wp);
        As[0][ldCol + 0][ldRow] = av.x;
        As[0][ldCol + 1][ldRow] = av.y;
        As[0][ldCol + 2][ldRow] = av.z;
        As[0][ldCol + 3][ldRow] = av.w;
        Bs[0][ldCol + 0][ldRow] = wv.x;
        Bs[0][ldCol + 1][ldRow] = wv.y;
        Bs[0][ldCol + 2][ldRow] = wv.z;
        Bs[0][ldCol + 3][ldRow] = wv.w;
    }
    __syncthreads();

    int buf = 0;
    for (int kt = 0; kt < E_; kt += 8) {
        const bool more = (kt + 8) < E_;
        float4 nav, nwv;
        if (more) {
            nav = *(const float4*)(Ap + kt + 8);   // issue early; latency hides
            nwv = *(const float4*)(Wp + kt + 8);   // behind the compute below
        }
#pragma unroll
        for (int k = 0; k < 8; k++) {
            const float4 a0 = *(const float4*)&As[buf][k][ty * 4];
            const float4 a1 = *(const float4*)&As[buf][k][64 + ty * 4];
            const float4 b0 = *(const float4*)&Bs[buf][k][tx * 4];
            const float4 b1 = *(const float4*)&Bs[buf][k][64 + tx * 4];
            const float am[8] = {a0.x, a0.y, a0.z, a0.w, a1.x, a1.y, a1.z, a1.w};
            const float bv[8] = {b0.x, b0.y, b0.z, b0.w, b1.x, b1.y, b1.z, b1.w};
#pragma unroll
            for (int i = 0; i < 8; i++)
#pragma unroll
                for (int j = 0; j < 8; j++)
                    acc[i][j] = fmaf(am[i], bv[j], acc[i][j]);
        }
        if (more) {
            const int nb = buf ^ 1;
            As[nb][ldCol + 0][ldRow] = nav.x;
            As[nb][ldCol + 1][ldRow] = nav.y;
            As[nb][ldCol + 2][ldRow] = nav.z;
            As[nb][ldCol + 3][ldRow] = nav.w;
            Bs[nb][ldCol + 0][ldRow] = nwv.x;
            Bs[nb][ldCol + 1][ldRow] = nwv.y;
            Bs[nb][ldCol + 2][ldRow] = nwv.z;
            Bs[nb][ldCol + 3][ldRow] = nwv.w;
            __syncthreads();
            buf = nb;
        }
    }

    const float4 bb0 = *(const float4*)&bias[bn + tx * 4];
    const float4 bb1 = *(const float4*)&bias[bn + 64 + tx * 4];
    const float bsum[8] = {bb0.x, bb0.y, bb0.z, bb0.w, bb1.x, bb1.y, bb1.z, bb1.w};

#pragma unroll
    for (int i = 0; i < 8; i++) {
        const int m = bm + ((i < 4) ? (ty * 4 + i) : (64 + ty * 4 + i - 4));
        float4 c0, c1;
        c0.x = acc[i][0] + bsum[0];
        c0.y = acc[i][1] + bsum[1];
        c0.z = acc[i][2] + bsum[2];
        c0.w = acc[i][3] + bsum[3];
        c1.x = acc[i][4] + bsum[4];
        c1.y = acc[i][5] + bsum[5];
        c1.z = acc[i][6] + bsum[6];
        c1.w = acc[i][7] + bsum[7];
        *(float4*)&C[(size_t)m * E_ + bn + tx * 4] = c0;
        *(float4*)&C[(size_t)m * E_ + bn + 64 + tx * 4] = c1;
    }
}

// ---------------------------------------------------------------------------
// Fused flash-style attention (fp32, unscaled scores, online softmax).
// Grid: (S/64, B*H). Block: 256 threads (16x16), 4x4 microtiles.
// Reads g_q/g_k/g_v, writes g_o. Layout: [S, B, E]; head (b,h) at offset
// b*E + h*HD, row stride RS_ = B*E.
// Shared: Qs[d][m], Ks[d][n], Vs[n][d], Pt[n][m], each 64x68 floats.
// Next chunk's K/V prefetched into registers during score compute.
// ---------------------------------------------------------------------------
#define ATT_SMEM_FLOATS (4 * 64 * 68)

__global__ void __launch_bounds__(256)
attn_kernel()
{
    extern __shared__ float sm[];
    float (*Qs)[68] = (float(*)[68])(sm);
    float (*Ks)[68] = (float(*)[68])(sm + 64 * 68);
    float (*Vs)[68] = (float(*)[68])(sm + 2 * 64 * 68);
    float (*Pt)[68] = (float(*)[68])(sm + 3 * 64 * 68);

    const int tid = threadIdx.x;
    const int tx = tid & 15;
    const int ty = tid >> 4;
    const int qb = blockIdx.x;       // query block (64 rows)
    const int bh = blockIdx.y;       // 0..B*H-1
    const int b = bh >> 4;           // H_=16
    const int h = bh & 15;

    const size_t headoff = (size_t)b * E_ + (size_t)h * HD_;
    const float* qp = (const float*)g_q + headoff;
    const float* kp = (const float*)g_k + headoff;
    const float* vp = (const float*)g_v + headoff;

    const int lr = tid >> 2;         // 0..63 (row for loads)
    const int seg = tid & 3;         // 0..3
    const int s0 = qb * 64;

    // Load Q block transposed: Qs[d][m]
#pragma unroll
    for (int t = 0; t < 4; t++) {
        const int d0 = seg * 4 + t * 16;
        const float4 v = *(const float4*)(qp + (size_t)(s0 + lr) * RS_ + d0);
        Qs[d0 + 0][lr] = v.x;
        Qs[d0 + 1][lr] = v.y;
        Qs[d0 + 2][lr] = v.z;
        Qs[d0 + 3][lr] = v.w;
    }

    float oacc[4][4];
    float run_m[4], run_s[4];
#pragma unroll
    for (int i = 0; i < 4; i++) {
        run_m[i] = -1e30f;
        run_s[i] = 0.f;
#pragma unroll
        for (int j = 0; j < 4; j++) oacc[i][j] = 0.f;
    }

    // Prefetch chunk 0 K/V into registers
    float4 krg[4], vrg[4];
#pragma unroll
    for (int t = 0; t < 4; t++) {
        const int d0 = seg * 4 + t * 16;
        krg[t] = *(const float4*)(kp + (size_t)lr * RS_ + d0);
        vrg[t] = *(const float4*)(vp + (size_t)lr * RS_ + d0);
    }

    const int NC = S_ / 64;
    for (int ch = 0; ch < NC; ch++) {
        __syncthreads();   // previous iteration's readers done with Ks/Vs/Pt
        // Commit prefetched K (transposed: Ks[d][n]) and V (direct: Vs[n][d])
#pragma unroll
        for (int t = 0; t < 4; t++) {
            const int d0 = seg * 4 + t * 16;
            Ks[d0 + 0][lr] = krg[t].x;
            Ks[d0 + 1][lr] = krg[t].y;
            Ks[d0 + 2][lr] = krg[t].z;
            Ks[d0 + 3][lr] = krg[t].w;
            *(float4*)&Vs[lr][d0] = vrg[t];
        }
        __syncthreads();

        // Issue next chunk's loads now; latency hidden behind score compute
        if (ch + 1 < NC) {
            const int n1 = (ch + 1) * 64;
#pragma unroll
            for (int t = 0; t < 4; t++) {
                const int d0 = seg * 4 + t * 16;
                krg[t] = *(const float4*)(kp + (size_t)(n1 + lr) * RS_ + d0);
                vrg[t] = *(const float4*)(vp + (size_t)(n1 + lr) * RS_ + d0);
            }
        }

        // Scores: sc[i][j] = sum_d Q[m=ty*4+i][d] * K[n=tx*4+j][d]
        float sc[4][4];
#pragma unroll
        for (int i = 0; i < 4; i++)
#pragma unroll
            for (int j = 0; j < 4; j++) sc[i][j] = 0.f;

#pragma unroll 8
        for (int d = 0; d < 64; d++) {
            const float4 q0 = *(const float4*)&Qs[d][ty * 4];
            const float4 k0 = *(const float4*)&Ks[d][tx * 4];
            const float qm[4] = {q0.x, q0.y, q0.z, q0.w};
            const float kn[4] = {k0.x, k0.y, k0.z, k0.w};
#pragma unroll
            for (int i = 0; i < 4; i++)
#pragma unroll
                for (int j = 0; j < 4; j++)
                    sc[i][j] = fmaf(qm[i], kn[j], sc[i][j]);
        }

        // Online softmax per row (16 threads sharing ty are a contiguous
        // 16-lane group within a warp -> xor-shuffle reduce over tx)
#pragma unroll
        for (int i = 0; i < 4; i++) {
            float cm = fmaxf(fmaxf(sc[i][0], sc[i][1]), fmaxf(sc[i][2], sc[i][3]));
            cm = fmaxf(cm, __shfl_xor_sync(0xffffffffu, cm, 1));
            cm = fmaxf(cm, __shfl_xor_sync(0xffffffffu, cm, 2));
            cm = fmaxf(cm, __shfl_xor_sync(0xffffffffu, cm, 4));
            cm = fmaxf(cm, __shfl_xor_sync(0xffffffffu, cm, 8));
            const float nm = fmaxf(run_m[i], cm);
            const float al = __expf(run_m[i] - nm);
            run_m[i] = nm;
            float ps = 0.f;
#pragma unroll
            for (int j = 0; j < 4; j++) {
                sc[i][j] = __expf(sc[i][j] - nm);
                ps += sc[i][j];
            }
            ps += __shfl_xor_sync(0xffffffffu, ps, 1);
            ps += __shfl_xor_sync(0xffffffffu, ps, 2);
            ps += __shfl_xor_sync(0xffffffffu, ps, 4);
            ps += __shfl_xor_sync(0xffffffffu, ps, 8);
            run_s[i] = run_s[i] * al + ps;
#pragma unroll
            for (int j = 0; j < 4; j++) oacc[i][j] *= al;
        }

        // Store P transposed: Pt[n][m] (float4 along m = thread's 4 rows)
#pragma unroll
        for (int j = 0; j < 4; j++) {
            float4 w;
            w.x = sc[0][j];
            w.y = sc[1][j];
            w.z = sc[2][j];
            w.w = sc[3][j];
            *(float4*)&Pt[tx * 4 + j][ty * 4] = w;
        }
        __syncthreads();

        // O[m][d] += sum_n P[m][n] * V[n][d]
#pragma unroll 8
        for (int n = 0; n < 64; n++) {
            const float4 pf = *(const float4*)&Pt[n][ty * 4];
            const float4 vv = *(const float4*)&Vs[n][tx * 4];
            const float pm[4] = {pf.x, pf.y, pf.z, pf.w};
            const float vd[4] = {vv.x, vv.y, vv.z, vv.w};
#pragma unroll
            for (int i = 0; i < 4; i++)
#pragma unroll
                for (int j = 0; j < 4; j++)
                    oacc[i][j] = fmaf(pm[i], vd[j], oacc[i][j]);
        }
    }

    // Normalize and write out (same [S,B,E] layout)
    float* op = (float*)g_o + headoff;
#pragma unroll
    for (int i = 0; i < 4; i++) {
        const float inv = 1.0f / run_s[i];
        float4 w;
        w.x = oacc[i][0] * inv;
        w.y = oacc[i][1] * inv;
        w.z = oacc[i][2] * inv;
        w.w = oacc[i][3] * inv;
        *(float4*)(op + (size_t)(s0 + ty * 4 + i) * RS_ + tx * 4) = w;
    }
}

// ---------------------------------------------------------------------------
// Launch: 5 kernel launches, no other stream-visible host API calls.
// ---------------------------------------------------------------------------
extern "C" void kernel_launch(void* const* d_in, const int* in_sizes, int n_in,
                              void* d_out, int out_size)
{
    (void)in_sizes; (void)n_in; (void)out_size;
    const float* query = (const float*)d_in[0];
    const float* key   = (const float*)d_in[1];
    const float* value = (const float*)d_in[2];
    const float* Wq    = (const float*)d_in[3];
    const float* bq    = (const float*)d_in[4];
    const float* Wk    = (const float*)d_in[5];
    const float* bk    = (const float*)d_in[6];
    const float* Wv    = (const float*)d_in[7];
    const float* bv    = (const float*)d_in[8];
    const float* Wo    = (const float*)d_in[9];
    const float* bo    = (const float*)d_in[10];
    float* out = (float*)d_out;

    const int smem_bytes = ATT_SMEM_FLOATS * (int)sizeof(float);  // 69632
    cudaFuncSetAttribute(attn_kernel, cudaFuncAttributeMaxDynamicSharedMemorySize,
                         smem_bytes);

    const dim3 ggrid(E_ / 128, M_ / 128);   // (8, 32)
    gemm_nt_bias<<<ggrid, 256>>>(query, Wq, bq, nullptr, 0, 0);
    gemm_nt_bias<<<ggrid, 256>>>(key,   Wk, bk, nullptr, 0, 1);
    gemm_nt_bias<<<ggrid, 256>>>(value, Wv, bv, nullptr, 0, 2);

    const dim3 agrid(S_ / 64, B_ * H_);     // (32, 32)
    attn_kernel<<<agrid, 256, smem_bytes>>>();

    gemm_nt_bias<<<ggrid, 256>>>(nullptr, Wo, bo, out, 1, 3);
}

// round 4
// speedup vs baseline: 1.2561x; 1.2561x over previous
#include <cuda_runtime.h>
#include <cuda_bf16.h>
#include <cstddef>
#include <cstdint>

// Problem constants
#define S_  2048
#define B_  2
#define E_  1024
#define H_  16
#define HD_ 64
#define M_  (S_ * B_)      // 4096 rows for projection GEMMs
#define RS_ (B_ * E_)      // 2048 floats: row stride in [S,B,E]

// Scratch buffers (device globals; no cudaMalloc allowed)
__device__ __align__(128) float g_q[(size_t)M_ * E_];
__device__ __align__(128) float g_k[(size_t)M_ * E_];
__device__ __align__(128) float g_v[(size_t)M_ * E_];
__device__ __align__(128) float g_o[(size_t)M_ * E_];

__device__ __forceinline__ float* pick_out(int w, float* ext) {
    switch (w) { case 0: return g_q; case 1: return g_k; case 2: return g_v; default: return ext; }
}
__device__ __forceinline__ const float* pick_in(int w, const float* ext) {
    return (w == 1) ? (const float*)g_o : ext;
}

// ---------------------------------------------------------------------------
// Base-ISA tensor-core primitives (sm_80+; legal in compute_100 base PTX)
// ---------------------------------------------------------------------------
__device__ __forceinline__ uint32_t smem_u32(const void* p) {
    uint32_t a;
    asm("{ .reg .u64 t; cvta.to.shared.u64 t, %1; cvt.u32.u64 %0, t; }" : "=r"(a) : "l"(p));
    return a;
}

#define LDM_X4(r, addr) \
    asm volatile("ldmatrix.sync.aligned.m8n8.x4.shared.b16 {%0,%1,%2,%3}, [%4];" \
                 : "=r"((r)[0]), "=r"((r)[1]), "=r"((r)[2]), "=r"((r)[3]) : "r"(addr))
#define LDM_X2(r, addr) \
    asm volatile("ldmatrix.sync.aligned.m8n8.x2.shared.b16 {%0,%1}, [%2];" \
                 : "=r"((r)[0]), "=r"((r)[1]) : "r"(addr))

__device__ __forceinline__ void mma16816(float* c, const uint32_t* a, const uint32_t* b)
{
    asm volatile("mma.sync.aligned.m16n8k16.row.col.f32.bf16.bf16.f32 "
                 "{%0,%1,%2,%3}, {%4,%5,%6,%7}, {%8,%9}, {%0,%1,%2,%3};"
                 : "+f"(c[0]), "+f"(c[1]), "+f"(c[2]), "+f"(c[3])
                 : "r"(a[0]), "r"(a[1]), "r"(a[2]), "r"(a[3]), "r"(b[0]), "r"(b[1]));
}

// Split fp32 pair into hi/lo bf16x2 words (x -> low half-word)
__device__ __forceinline__ void split2(float x, float y, uint32_t& hi, uint32_t& lo)
{
    __nv_bfloat16 hx = __float2bfloat16(x);
    __nv_bfloat16 hy = __float2bfloat16(y);
    __nv_bfloat16 lx = __float2bfloat16(x - __bfloat162float(hx));
    __nv_bfloat16 ly = __float2bfloat16(y - __bfloat162float(hy));
    __nv_bfloat162 hh; hh.x = hx; hh.y = hy;
    __nv_bfloat162 ll; ll.x = lx; ll.y = ly;
    hi = *reinterpret_cast<uint32_t*>(&hh);
    lo = *reinterpret_cast<uint32_t*>(&ll);
}

// ---------------------------------------------------------------------------
// HMMA projection GEMM, 2-term bf16 split.
// C[m,n] = sum_k A[m,k]*W[n,k] + bias[n].
// Tile 128x128, BK=32, 256 threads (8 warps, each 64x32 output).
// Smem per stage: 4 matrices (Ah,Al,Bh,Bl) of 128 rows x 40 bf16 (80B stride,
// conflict-free for ldmatrix). Double-buffered; one __syncthreads per chunk.
// ---------------------------------------------------------------------------
#define ROWB      80                       // bytes per smem row (32 bf16 + pad)
#define MATB      (128 * ROWB)             // 10240 B per matrix
#define STAGEB    (4 * MATB)               // 40960 B per stage
#define GEMM_DYN_SMEM (2 * STAGEB)         // 81920 B

__global__ void __launch_bounds__(256)
mma_gemm(const float* __restrict__ Aext, const float* __restrict__ W,
         const float* __restrict__ bias, float* __restrict__ Cext,
         int which_in, int which_out)
{
    extern __shared__ char dynsm[];
    const float* A = pick_in(which_in, Aext);
    float* C = pick_out(which_out, Cext);

    const int tid  = threadIdx.x;
    const int wid  = tid >> 5;
    const int lane = tid & 31;
    const int bm = blockIdx.y * 128;
    const int bn = blockIdx.x * 128;

    const int wm0 = (wid & 1) * 64;    // warp m offset within tile
    const int wn0 = (wid >> 1) * 32;   // warp n offset within tile

    const uint32_t smbase = smem_u32(dynsm);

    // Loader mapping: row = tid>>1 (0..127), cols (tid&1)*16 .. +15 (fp32)
    const int lrow = tid >> 1;
    const int lc0  = (tid & 1) * 16;
    const float* Ap = A + (size_t)(bm + lrow) * E_ + lc0;
    const float* Wp = W + (size_t)(bn + lrow) * E_ + lc0;
    const int sdst = lrow * ROWB + lc0 * 2;   // byte offset within a matrix

    float acc[4][4][4];
#pragma unroll
    for (int mt = 0; mt < 4; mt++)
#pragma unroll
        for (int nt = 0; nt < 4; nt++)
#pragma unroll
            for (int q = 0; q < 4; q++) acc[mt][nt][q] = 0.f;

    float4 pa[4], pw[4];
#pragma unroll
    for (int t = 0; t < 4; t++) {
        pa[t] = *(const float4*)(Ap + t * 4);
        pw[t] = *(const float4*)(Wp + t * 4);
    }

    // convert current prefetch regs and store into stage `buf`
    auto cvst = [&](int buf) {
        char* st = dynsm + buf * STAGEB;
        uint32_t h[8], l[8];
#pragma unroll
        for (int t = 0; t < 4; t++) {
            split2(pa[t].x, pa[t].y, h[2 * t], l[2 * t]);
            split2(pa[t].z, pa[t].w, h[2 * t + 1], l[2 * t + 1]);
        }
        *(uint4*)(st + 0 * MATB + sdst)      = make_uint4(h[0], h[1], h[2], h[3]);
        *(uint4*)(st + 0 * MATB + sdst + 16) = make_uint4(h[4], h[5], h[6], h[7]);
        *(uint4*)(st + 1 * MATB + sdst)      = make_uint4(l[0], l[1], l[2], l[3]);
        *(uint4*)(st + 1 * MATB + sdst + 16) = make_uint4(l[4], l[5], l[6], l[7]);
#pragma unroll
        for (int t = 0; t < 4; t++) {
            split2(pw[t].x, pw[t].y, h[2 * t], l[2 * t]);
            split2(pw[t].z, pw[t].w, h[2 * t + 1], l[2 * t + 1]);
        }
        *(uint4*)(st + 2 * MATB + sdst)      = make_uint4(h[0], h[1], h[2], h[3]);
        *(uint4*)(st + 2 * MATB + sdst + 16) = make_uint4(h[4], h[5], h[6], h[7]);
        *(uint4*)(st + 3 * MATB + sdst)      = make_uint4(l[0], l[1], l[2], l[3]);
        *(uint4*)(st + 3 * MATB + sdst + 16) = make_uint4(l[4], l[5], l[6], l[7]);
    };

    cvst(0);
    __syncthreads();

    const int NCH = E_ / 32;    // 32 chunks of BK=32
    // Per-thread ldmatrix address components (byte offsets within a matrix)
    const uint32_t a_row_off = (uint32_t)(wm0 + (lane & 15)) * ROWB + ((lane >> 4) * 16);
    const uint32_t b_row_off = (uint32_t)(wn0 + (lane & 7)) * ROWB + (((lane >> 3) & 1) * 16);

    for (int ch = 0; ch < NCH; ch++) {
        const bool more = (ch + 1) < NCH;
        if (more) {
            const int kt = (ch + 1) * 32;
#pragma unroll
            for (int t = 0; t < 4; t++) {
                pa[t] = *(const float4*)(Ap + kt + t * 4);
                pw[t] = *(const float4*)(Wp + kt + t * 4);
            }
        }
        const uint32_t sb = smbase + (uint32_t)(ch & 1) * STAGEB;
#pragma unroll
        for (int ks = 0; ks < 2; ks++) {
            const uint32_t ko = (uint32_t)ks * 32;   // 16 bf16 = 32 B
            uint32_t ah[4][4], al[4][4];
#pragma unroll
            for (int mt = 0; mt < 4; mt++) {
                const uint32_t ad = sb + a_row_off + (uint32_t)(mt * 16) * ROWB + ko;
                LDM_X4(ah[mt], ad);
                LDM_X4(al[mt], ad + MATB);
            }
            uint32_t bh[4][2], bl[4][2];
#pragma unroll
            for (int nt = 0; nt < 4; nt++) {
                const uint32_t bd = sb + 2 * MATB + b_row_off + (uint32_t)(nt * 8) * ROWB + ko;
                LDM_X2(bh[nt], bd);
                LDM_X2(bl[nt], bd + MATB);
            }
#pragma unroll
            for (int mt = 0; mt < 4; mt++)
#pragma unroll
                for (int nt = 0; nt < 4; nt++) {
                    mma16816(acc[mt][nt], ah[mt], bh[nt]);
                    mma16816(acc[mt][nt], ah[mt], bl[nt]);
                    mma16816(acc[mt][nt], al[mt], bh[nt]);
                }
        }
        if (more) cvst((ch + 1) & 1);
        __syncthreads();
    }

    // Epilogue: c0,c1 -> row g, cols cc,cc+1 ; c2,c3 -> row g+8
    const int g  = lane >> 2;
    const int cc = (lane & 3) * 2;
#pragma unroll
    for (int nt = 0; nt < 4; nt++) {
        const int col = bn + wn0 + nt * 8 + cc;
        const float2 bv = *(const float2*)&bias[col];
#pragma unroll
        for (int mt = 0; mt < 4; mt++) {
            const int row0 = bm + wm0 + mt * 16 + g;
            float2 o0, o1;
            o0.x = acc[mt][nt][0] + bv.x;
            o0.y = acc[mt][nt][1] + bv.y;
            o1.x = acc[mt][nt][2] + bv.x;
            o1.y = acc[mt][nt][3] + bv.y;
            *(float2*)&C[(size_t)row0 * E_ + col] = o0;
            *(float2*)&C[(size_t)(row0 + 8) * E_ + col] = o1;
        }
    }
}

// ---------------------------------------------------------------------------
// Fused flash-style attention (fp32, unscaled, online softmax) — unchanged R2
// ---------------------------------------------------------------------------
#define ATT_SMEM_FLOATS (4 * 64 * 68)

__global__ void __launch_bounds__(256)
attn_kernel()
{
    extern __shared__ float sm[];
    float (*Qs)[68] = (float(*)[68])(sm);
    float (*Ks)[68] = (float(*)[68])(sm + 64 * 68);
    float (*Vs)[68] = (float(*)[68])(sm + 2 * 64 * 68);
    float (*Pt)[68] = (float(*)[68])(sm + 3 * 64 * 68);

    const int tid = threadIdx.x;
    const int tx = tid & 15;
    const int ty = tid >> 4;
    const int qb = blockIdx.x;
    const int bh = blockIdx.y;
    const int b = bh >> 4;
    const int h = bh & 15;

    const size_t headoff = (size_t)b * E_ + (size_t)h * HD_;
    const float* qp = (const float*)g_q + headoff;
    const float* kp = (const float*)g_k + headoff;
    const float* vp = (const float*)g_v + headoff;

    const int lr = tid >> 2;
    const int seg = tid & 3;
    const int s0 = qb * 64;

#pragma unroll
    for (int t = 0; t < 4; t++) {
        const int d0 = seg * 4 + t * 16;
        const float4 v = *(const float4*)(qp + (size_t)(s0 + lr) * RS_ + d0);
        Qs[d0 + 0][lr] = v.x;
        Qs[d0 + 1][lr] = v.y;
        Qs[d0 + 2][lr] = v.z;
        Qs[d0 + 3][lr] = v.w;
    }

    float oacc[4][4];
    float run_m[4], run_s[4];
#pragma unroll
    for (int i = 0; i < 4; i++) {
        run_m[i] = -1e30f;
        run_s[i] = 0.f;
#pragma unroll
        for (int j = 0; j < 4; j++) oacc[i][j] = 0.f;
    }

    float4 krg[4], vrg[4];
#pragma unroll
    for (int t = 0; t < 4; t++) {
        const int d0 = seg * 4 + t * 16;
        krg[t] = *(const float4*)(kp + (size_t)lr * RS_ + d0);
        vrg[t] = *(const float4*)(vp + (size_t)lr * RS_ + d0);
    }

    const int NC = S_ / 64;
    for (int ch = 0; ch < NC; ch++) {
        __syncthreads();
#pragma unroll
        for (int t = 0; t < 4; t++) {
            const int d0 = seg * 4 + t * 16;
            Ks[d0 + 0][lr] = krg[t].x;
            Ks[d0 + 1][lr] = krg[t].y;
            Ks[d0 + 2][lr] = krg[t].z;
            Ks[d0 + 3][lr] = krg[t].w;
            *(float4*)&Vs[lr][d0] = vrg[t];
        }
        __syncthreads();

        if (ch + 1 < NC) {
            const int n1 = (ch + 1) * 64;
#pragma unroll
            for (int t = 0; t < 4; t++) {
                const int d0 = seg * 4 + t * 16;
                krg[t] = *(const float4*)(kp + (size_t)(n1 + lr) * RS_ + d0);
                vrg[t] = *(const float4*)(vp + (size_t)(n1 + lr) * RS_ + d0);
            }
        }

        float sc[4][4];
#pragma unroll
        for (int i = 0; i < 4; i++)
#pragma unroll
            for (int j = 0; j < 4; j++) sc[i][j] = 0.f;

#pragma unroll 8
        for (int d = 0; d < 64; d++) {
            const float4 q0 = *(const float4*)&Qs[d][ty * 4];
            const float4 k0 = *(const float4*)&Ks[d][tx * 4];
            const float qm[4] = {q0.x, q0.y, q0.z, q0.w};
            const float kn[4] = {k0.x, k0.y, k0.z, k0.w};
#pragma unroll
            for (int i = 0; i < 4; i++)
#pragma unroll
                for (int j = 0; j < 4; j++)
                    sc[i][j] = fmaf(qm[i], kn[j], sc[i][j]);
        }

#pragma unroll
        for (int i = 0; i < 4; i++) {
            float cm = fmaxf(fmaxf(sc[i][0], sc[i][1]), fmaxf(sc[i][2], sc[i][3]));
            cm = fmaxf(cm, __shfl_xor_sync(0xffffffffu, cm, 1));
            cm = fmaxf(cm, __shfl_xor_sync(0xffffffffu, cm, 2));
            cm = fmaxf(cm, __shfl_xor_sync(0xffffffffu, cm, 4));
            cm = fmaxf(cm, __shfl_xor_sync(0xffffffffu, cm, 8));
            const float nm = fmaxf(run_m[i], cm);
            const float al = __expf(run_m[i] - nm);
            run_m[i] = nm;
            float ps = 0.f;
#pragma unroll
            for (int j = 0; j < 4; j++) {
                sc[i][j] = __expf(sc[i][j] - nm);
                ps += sc[i][j];
            }
            ps += __shfl_xor_sync(0xffffffffu, ps, 1);
            ps += __shfl_xor_sync(0xffffffffu, ps, 2);
            ps += __shfl_xor_sync(0xffffffffu, ps, 4);
            ps += __shfl_xor_sync(0xffffffffu, ps, 8);
            run_s[i] = run_s[i] * al + ps;
#pragma unroll
            for (int j = 0; j < 4; j++) oacc[i][j] *= al;
        }

#pragma unroll
        for (int j = 0; j < 4; j++) {
            float4 w;
            w.x = sc[0][j];
            w.y = sc[1][j];
            w.z = sc[2][j];
            w.w = sc[3][j];
            *(float4*)&Pt[tx * 4 + j][ty * 4] = w;
        }
        __syncthreads();

#pragma unroll 8
        for (int n = 0; n < 64; n++) {
            const float4 pf = *(const float4*)&Pt[n][ty * 4];
            const float4 vv = *(const float4*)&Vs[n][tx * 4];
            const float pm[4] = {pf.x, pf.y, pf.z, pf.w};
            const float vd[4] = {vv.x, vv.y, vv.z, vv.w};
#pragma unroll
            for (int i = 0; i < 4; i++)
#pragma unroll
                for (int j = 0; j < 4; j++)
                    oacc[i][j] = fmaf(pm[i], vd[j], oacc[i][j]);
        }
    }

    float* op = (float*)g_o + headoff;
#pragma unroll
    for (int i = 0; i < 4; i++) {
        const float inv = 1.0f / run_s[i];
        float4 w;
        w.x = oacc[i][0] * inv;
        w.y = oacc[i][1] * inv;
        w.z = oacc[i][2] * inv;
        w.w = oacc[i][3] * inv;
        *(float4*)(op + (size_t)(s0 + ty * 4 + i) * RS_ + tx * 4) = w;
    }
}

// ---------------------------------------------------------------------------
// Launch
// ---------------------------------------------------------------------------
extern "C" void kernel_launch(void* const* d_in, const int* in_sizes, int n_in,
                              void* d_out, int out_size)
{
    (void)in_sizes; (void)n_in; (void)out_size;
    const float* query = (const float*)d_in[0];
    const float* key   = (const float*)d_in[1];
    const float* value = (const float*)d_in[2];
    const float* Wq    = (const float*)d_in[3];
    const float* bq    = (const float*)d_in[4];
    const float* Wk    = (const float*)d_in[5];
    const float* bk    = (const float*)d_in[6];
    const float* Wv    = (const float*)d_in[7];
    const float* bv    = (const float*)d_in[8];
    const float* Wo    = (const float*)d_in[9];
    const float* bo    = (const float*)d_in[10];
    float* out = (float*)d_out;

    const int att_smem = ATT_SMEM_FLOATS * (int)sizeof(float);   // 69632
    cudaFuncSetAttribute(attn_kernel, cudaFuncAttributeMaxDynamicSharedMemorySize, att_smem);
    cudaFuncSetAttribute(mma_gemm, cudaFuncAttributeMaxDynamicSharedMemorySize, GEMM_DYN_SMEM);

    const dim3 ggrid(E_ / 128, M_ / 128);   // (8, 32) = 256 CTAs
    mma_gemm<<<ggrid, 256, GEMM_DYN_SMEM>>>(query, Wq, bq, nullptr, 0, 0);
    mma_gemm<<<ggrid, 256, GEMM_DYN_SMEM>>>(key,   Wk, bk, nullptr, 0, 1);
    mma_gemm<<<ggrid, 256, GEMM_DYN_SMEM>>>(value, Wv, bv, nullptr, 0, 2);

    const dim3 agrid(S_ / 64, B_ * H_);     // (32, 32)
    attn_kernel<<<agrid, 256, att_smem>>>();

    mma_gemm<<<ggrid, 256, GEMM_DYN_SMEM>>>(nullptr, Wo, bo, out, 1, 3);
}